// round 16
// baseline (speedup 1.0000x reference)
#include <cuda_runtime.h>
#include <cuda_fp16.h>
#include <cstdint>
#include <cstddef>

#define D        128
#define NNODES   1000000
#define BATCH    100000
#define NITER    6
#define GATES    512
#define KDIM     256

#define BM 256
#define MT 391                         // m-tiles of 256 rows
#define TPC 4                          // tiles per CTA
#define MG 98                          // ceil(391/4)
#define ROWPAD 100096                  // 391*256
#define PLANEH ((size_t)ROWPAD * 8)    // u32 per chunk plane (fp16)

// smem: B 64 rows x 528 B = 33792 | A 2 stages x 16 KB = 32768
#define SM_B     0
#define SM_A     33792
#define SMEM_GEMM 66560

// ---------------- device scratch ----------------
// A fp16, CHUNK-MAJOR: [parity][chunk 0..15][row][8 u32 = 16 fp16]
__device__ __align__(16) uint32_t g_Ah[2][16 * PLANEH];   // .bss zero; padding rows stay zero
__device__ float          g_h[BATCH * D];
__device__ float          g_c[BATCH * D];
__device__ __align__(16) __half g_Wh[GATES * KDIM];       // gate-permuted fp16 weights
__device__ float          g_bias[GATES];                   // gate-permuted
__device__ int            g_segstart[BATCH + 1];

// ---------------- helpers ----------------
__device__ __forceinline__ uint32_t pkhf(float a, float b) {
    __half2 h = __floats2half2_rn(a, b);
    return *reinterpret_cast<uint32_t*>(&h);
}
__device__ __forceinline__ float sigm(float v) { return 1.f / (1.f + __expf(-v)); }
__device__ __forceinline__ float ftanh(float v) { return 1.f - 2.f / (__expf(2.f * v) + 1.f); }

__device__ __forceinline__ void mma_fp16(float* d, const uint32_t* a, uint32_t b0, uint32_t b1) {
    asm volatile(
        "mma.sync.aligned.m16n8k16.row.col.f32.f16.f16.f32 "
        "{%0,%1,%2,%3}, {%4,%5,%6,%7}, {%8,%9}, {%0,%1,%2,%3};\n"
        : "+f"(d[0]), "+f"(d[1]), "+f"(d[2]), "+f"(d[3])
        : "r"(a[0]), "r"(a[1]), "r"(a[2]), "r"(a[3]), "r"(b0), "r"(b1));
}
__device__ __forceinline__ void ldsm4(uint32_t& r0, uint32_t& r1, uint32_t& r2, uint32_t& r3,
                                      uint32_t addr) {
    asm volatile("ldmatrix.sync.aligned.m8n8.x4.shared.b16 {%0,%1,%2,%3}, [%4];"
                 : "=r"(r0), "=r"(r1), "=r"(r2), "=r"(r3) : "r"(addr));
}
__device__ __forceinline__ void cpa16s(uint32_t saddr, const void* g) {
    asm volatile("cp.async.cg.shared.global [%0], [%1], 16;\n" :: "r"(saddr), "l"(g));
}
#define CPA_COMMIT asm volatile("cp.async.commit_group;\n" ::: "memory")
#define CPA_WAIT0  asm volatile("cp.async.wait_group 0;\n" ::: "memory")

// ---------------- setup ----------------
__global__ void k_segstart(const void* batch) {
    int n = blockIdx.x * blockDim.x + threadIdx.x;
    if (n >= NNODES) return;
    const int* p32 = (const int*)batch;
    bool is64 = (p32[500001] == 0 && p32[700001] == 0 && p32[900001] == 0);
    int cur, prev;
    if (is64) {
        const long long* p64 = (const long long*)batch;
        cur  = (int)p64[n];
        prev = (n == 0) ? -1 : (int)p64[n - 1];
    } else {
        cur  = p32[n];
        prev = (n == 0) ? -1 : p32[n - 1];
    }
    for (int b = prev + 1; b <= cur; ++b) g_segstart[b] = n;
    if (n == NNODES - 1)
        for (int b = cur + 1; b <= BATCH; ++b) g_segstart[b] = NNODES;
}

// perm: p = bn*64 + gt*16 + j  <->  n = gt*128 + bn*16 + j
__global__ void k_prep(const float* __restrict__ w_ih, const float* __restrict__ w_hh,
                       const float* __restrict__ b_ih, const float* __restrict__ b_hh) {
    int i = blockIdx.x * blockDim.x + threadIdx.x;
    if (i < GATES * KDIM) {
        int p = i / KDIM, k = i % KDIM;
        int bn = p >> 6, rem = p & 63, gt = rem >> 4, j = rem & 15;
        int n = gt * 128 + bn * 16 + j;
        float w = w_ih[n * KDIM + k];
        if (k < D) w += w_hh[n * D + k];
        g_Wh[i] = __float2half_rn(w);
    }
    if (i < GATES) {
        int bn = i >> 6, rem = i & 63, gt = rem >> 4, j = rem & 15;
        int n = gt * 128 + bn * 16 + j;
        g_bias[i] = b_ih[n] + b_hh[n];
    }
}

// ---------------- attention core: max-free, 8 nodes / iteration (R11 structure) ----------------
// If outp != nullptr (final iteration), write q_star = [h | readout] directly; else write
// the fp16 readout into the A staging planes for the next GEMM.
__device__ __forceinline__ void attn_core(const float* __restrict__ x, int b,
                                          int s0, int s1, int lane,
                                          const float4 hv[4], uint32_t* Ad32,
                                          float* outp) {
    int nsub = lane & 3, q = lane >> 2;
    const float4* x4 = (const float4*)x;
    const float4 z4 = make_float4(0.f, 0.f, 0.f, 0.f);
    float ssum = 0.f;
    float4 acc[4];
    #pragma unroll
    for (int j = 0; j < 4; ++j) acc[j] = z4;

    for (int base = s0; base < s1; base += 8) {
        int na = base + nsub, nb = base + 4 + nsub;
        bool va = na < s1, vb = nb < s1;
        float4 xv[4], yv[4];
        if (va) {
            size_t off = (size_t)na * 32 + q * 4;
            #pragma unroll
            for (int j = 0; j < 4; ++j) xv[j] = x4[off + j];
        } else {
            #pragma unroll
            for (int j = 0; j < 4; ++j) xv[j] = z4;
        }
        if (vb) {
            size_t off = (size_t)nb * 32 + q * 4;
            #pragma unroll
            for (int j = 0; j < 4; ++j) yv[j] = x4[off + j];
        } else {
            #pragma unroll
            for (int j = 0; j < 4; ++j) yv[j] = z4;
        }

        float p1 = 0.f, p2 = 0.f;
        #pragma unroll
        for (int j = 0; j < 4; ++j) {
            p1 += xv[j].x * hv[j].x + xv[j].y * hv[j].y + xv[j].z * hv[j].z + xv[j].w * hv[j].w;
            p2 += yv[j].x * hv[j].x + yv[j].y * hv[j].y + yv[j].z * hv[j].z + yv[j].w * hv[j].w;
        }
        #pragma unroll
        for (int st = 4; st <= 16; st <<= 1) {
            p1 += __shfl_xor_sync(0xffffffffu, p1, st);
            p2 += __shfl_xor_sync(0xffffffffu, p2, st);
        }
        float a1 = va ? __expf(p1 - 20.f) : 0.f;
        float a2 = vb ? __expf(p2 - 20.f) : 0.f;
        ssum += a1 + a2;
        #pragma unroll
        for (int j = 0; j < 4; ++j) {
            acc[j].x += a1 * xv[j].x + a2 * yv[j].x;
            acc[j].y += a1 * xv[j].y + a2 * yv[j].y;
            acc[j].z += a1 * xv[j].z + a2 * yv[j].z;
            acc[j].w += a1 * xv[j].w + a2 * yv[j].w;
        }
    }

    #pragma unroll
    for (int j = 0; j < 4; ++j) {
        #pragma unroll
        for (int st = 1; st < 4; st <<= 1) {
            acc[j].x += __shfl_xor_sync(0xffffffffu, acc[j].x, st);
            acc[j].y += __shfl_xor_sync(0xffffffffu, acc[j].y, st);
            acc[j].z += __shfl_xor_sync(0xffffffffu, acc[j].z, st);
            acc[j].w += __shfl_xor_sync(0xffffffffu, acc[j].w, st);
        }
    }
    ssum += __shfl_xor_sync(0xffffffffu, ssum, 1);
    ssum += __shfl_xor_sync(0xffffffffu, ssum, 2);
    float inv = (ssum > 0.f) ? 1.f / ssum : 0.f;

    if (nsub == 0) {
        if (outp) {
            float4* o4 = (float4*)outp;
            #pragma unroll
            for (int j = 0; j < 4; ++j) o4[(size_t)b * 64 + q * 4 + j] = hv[j];
            #pragma unroll
            for (int j = 0; j < 4; ++j) {
                float4 v2 = acc[j];
                v2.x *= inv; v2.y *= inv; v2.z *= inv; v2.w *= inv;
                o4[(size_t)b * 64 + 32 + q * 4 + j] = v2;
            }
        } else {
            float f[16];
            #pragma unroll
            for (int j = 0; j < 4; ++j) {
                f[j * 4]     = acc[j].x * inv;
                f[j * 4 + 1] = acc[j].y * inv;
                f[j * 4 + 2] = acc[j].z * inv;
                f[j * 4 + 3] = acc[j].w * inv;
            }
            uint32_t hi[8];
            #pragma unroll
            for (int u = 0; u < 8; ++u) hi[u] = pkhf(f[2 * u], f[2 * u + 1]);
            uint4* dst = (uint4*)(Ad32 + (size_t)(8 + q) * PLANEH + (size_t)b * 8);
            dst[0] = make_uint4(hi[0], hi[1], hi[2], hi[3]);
            dst[1] = make_uint4(hi[4], hi[5], hi[6], hi[7]);
        }
    }
}

#define WPB 8
__global__ __launch_bounds__(WPB * 32, 3) void k_attn0(const float* __restrict__ x,
                                                       const float* __restrict__ b_ih,
                                                       const float* __restrict__ b_hh) {
    int warp = threadIdx.x >> 5, lane = threadIdx.x & 31;
    int b = blockIdx.x * WPB + warp;
    if (b >= BATCH) return;
    int nsub = lane & 3, q = lane >> 2;

    float hvf[16], cvf[16];
    #pragma unroll
    for (int t = 0; t < 16; ++t) {
        int d = q * 16 + t;
        float gi = b_ih[d]       + b_hh[d];
        float gg = b_ih[256 + d] + b_hh[256 + d];
        float go = b_ih[384 + d] + b_hh[384 + d];
        float c  = sigm(gi) * ftanh(gg);
        cvf[t] = c;
        hvf[t] = sigm(go) * ftanh(c);
    }
    float4 hv[4];
    #pragma unroll
    for (int j = 0; j < 4; ++j)
        hv[j] = make_float4(hvf[j * 4], hvf[j * 4 + 1], hvf[j * 4 + 2], hvf[j * 4 + 3]);

    uint32_t* Ad32 = g_Ah[1];
    if (nsub == 0) {
        #pragma unroll
        for (int j = 0; j < 4; ++j) {
            ((float4*)g_h)[b * 32 + q * 4 + j] = hv[j];
            ((float4*)g_c)[b * 32 + q * 4 + j] =
                make_float4(cvf[j * 4], cvf[j * 4 + 1], cvf[j * 4 + 2], cvf[j * 4 + 3]);
        }
        uint32_t hi[8];
        #pragma unroll
        for (int u = 0; u < 8; ++u) hi[u] = pkhf(hvf[2 * u], hvf[2 * u + 1]);
        uint4* dst = (uint4*)(Ad32 + (size_t)q * PLANEH + (size_t)b * 8);
        dst[0] = make_uint4(hi[0], hi[1], hi[2], hi[3]);
        dst[1] = make_uint4(hi[4], hi[5], hi[6], hi[7]);
    }

    int s0 = g_segstart[b], s1 = g_segstart[b + 1];
    attn_core(x, b, s0, s1, lane, hv, Ad32, nullptr);
}

__global__ __launch_bounds__(WPB * 32, 3) void k_attn(const float* __restrict__ x, int pn) {
    int warp = threadIdx.x >> 5, lane = threadIdx.x & 31;
    int b = blockIdx.x * WPB + warp;
    if (b >= BATCH) return;
    int q = lane >> 2;
    float4 hv[4];
    #pragma unroll
    for (int j = 0; j < 4; ++j) hv[j] = ((const float4*)g_h)[b * 32 + q * 4 + j];
    int s0 = g_segstart[b], s1 = g_segstart[b + 1];
    attn_core(x, b, s0, s1, lane, hv, g_Ah[pn], nullptr);
}

// final-iteration variant: separate kernel so k_attn's register allocation is untouched
__global__ __launch_bounds__(WPB * 32, 3) void k_attn_last(const float* __restrict__ x,
                                                           float* __restrict__ outp) {
    int warp = threadIdx.x >> 5, lane = threadIdx.x & 31;
    int b = blockIdx.x * WPB + warp;
    if (b >= BATCH) return;
    int q = lane >> 2;
    float4 hv[4];
    #pragma unroll
    for (int j = 0; j < 4; ++j) hv[j] = ((const float4*)g_h)[b * 32 + q * 4 + j];
    int s0 = g_segstart[b], s1 = g_segstart[b + 1];
    attn_core(x, b, s0, s1, lane, hv, nullptr, outp);
}

// ---------------- fused GEMM + LSTM: fp16 1-pass, multi-tile CTA, 2-stage pipeline ----------------
// grid (8, MG): each CTA keeps its B tile resident and walks TPC=4 m-tiles; the A cp.async
// pipeline runs continuously across tile boundaries; the per-tile LSTM epilogue overlaps the
// next tile's loads.
__global__ __launch_bounds__(256, 2) void k_gemm(int p) {
    extern __shared__ char smem[];
    uint32_t sb = (uint32_t)__cvta_generic_to_shared(smem);
    const uint32_t* Asrc = g_Ah[p];
    uint32_t*       Ad32 = g_Ah[p ^ 1];

    int bn = blockIdx.x, by = blockIdx.y;
    int tid = threadIdx.x, w = tid >> 5, lane = tid & 31;
    int gi = lane >> 3, lr = lane & 7;
    int g = lane >> 2, t4 = lane & 3;

    int t0 = by * TPC;
    int ntiles = MT - t0; if (ntiles > TPC) ntiles = TPC;
    int nph = ntiles * 8;

    // resident B: 64 rows x 512B, stride 528
    {
        const char* Wb = (const char*)(g_Wh + (size_t)(bn * 64) * KDIM);
        #pragma unroll
        for (int t = 0; t < 8; ++t) {
            int e = t * 256 + tid;
            int r = e >> 5, u = e & 31;
            cpa16s(sb + SM_B + r * 528 + u * 16, Wb + (size_t)r * 512 + u * 16);
        }
    }

    // A pipeline bases
    uint32_t pu_cp = (tid & 1) ^ ((tid >> 3) & 1);
    uint32_t dA = sb + SM_A + (tid >> 1) * 32 + pu_cp * 16;
    const char* Abase = (const char*)Asrc + (tid >> 1) * 32 + (tid & 1) * 16;

    // stage s: tile ts = s>>3 (8192 B per tile within a chunk plane), chunks 2*(s&7), +1
    #define LOAD_STAGE(s)  do {                                                        \
        const char* sAp = Abase + (size_t)(t0 + ((s) >> 3)) * 8192                     \
                                + (size_t)((s) & 7) * 2 * (PLANEH * 4);                \
        uint32_t dA2 = dA + ((s) & 1) * 16384;                                         \
        _Pragma("unroll")                                                              \
        for (int t = 0; t < 4; ++t)                                                    \
            cpa16s(dA2 + t * 4096,                                                     \
                   sAp + (size_t)(t >> 1) * (PLANEH * 4) + (t & 1) * 4096);            \
        CPA_COMMIT;                                                                    \
    } while (0)

    LOAD_STAGE(0);

    float acc[2][8][4];
    #pragma unroll
    for (int mf = 0; mf < 2; ++mf)
        #pragma unroll
        for (int nf = 0; nf < 8; ++nf)
            #pragma unroll
            for (int v = 0; v < 4; ++v) acc[mf][nf][v] = 0.f;

    // loop-invariant addresses + bias
    uint32_t aoff[2];
    #pragma unroll
    for (int mf = 0; mf < 2; ++mf) {
        int rowA = w * 32 + mf * 16 + (gi & 1) * 8 + lr;
        aoff[mf] = rowA * 32 + (((gi >> 1) ^ ((rowA >> 2) & 1)) << 4);
    }
    uint32_t bbase = sb + SM_B + ((gi & 1) * 8 + lr) * 528 + (gi >> 1) * 16;

    float2 bv[4][2];
    #pragma unroll
    for (int gt = 0; gt < 4; ++gt)
        #pragma unroll
        for (int jf = 0; jf < 2; ++jf)
            bv[gt][jf] = *(const float2*)&g_bias[bn * 64 + gt * 16 + jf * 8 + t4 * 2];

    #pragma unroll 1
    for (int s = 0; s < nph; ++s) {
        CPA_WAIT0;
        __syncthreads();
        if (s + 1 < nph) LOAD_STAGE(s + 1);

        uint32_t ab = sb + SM_A + (s & 1) * 16384;
        int ps = s & 7;
        #pragma unroll
        for (int c = 0; c < 2; ++c) {
            int kc = ps * 2 + c;
            uint32_t ah[2][4], bb[4][4];
            #pragma unroll
            for (int mf = 0; mf < 2; ++mf)
                ldsm4(ah[mf][0], ah[mf][1], ah[mf][2], ah[mf][3], ab + c * 8192 + aoff[mf]);
            #pragma unroll
            for (int np = 0; np < 4; ++np)
                ldsm4(bb[np][0], bb[np][1], bb[np][2], bb[np][3], bbase + np * 8448 + kc * 32);
            #pragma unroll
            for (int mf = 0; mf < 2; ++mf)
                #pragma unroll
                for (int nf = 0; nf < 8; ++nf) {
                    int np = nf >> 1, od = nf & 1;
                    mma_fp16(acc[mf][nf], ah[mf], bb[np][od], bb[np][od + 2]);
                }
        }

        // tile boundary: LSTM epilogue (overlaps the already-committed next-tile loads)
        if (ps == 7) {
            int row0 = (t0 + (s >> 3)) * BM;
            int rbase = row0 + w * 32 + g;
            #pragma unroll
            for (int mf = 0; mf < 2; ++mf) {
                #pragma unroll
                for (int half = 0; half < 2; ++half) {
                    int row = rbase + mf * 16 + half * 8;
                    if (row >= BATCH) continue;
                    #pragma unroll
                    for (int jf = 0; jf < 2; ++jf) {
                        int v = half * 2;
                        float gi0 = acc[mf][jf][v]         + bv[0][jf].x;
                        float gi1 = acc[mf][jf][v + 1]     + bv[0][jf].y;
                        float gf0 = acc[mf][2 + jf][v]     + bv[1][jf].x;
                        float gf1 = acc[mf][2 + jf][v + 1] + bv[1][jf].y;
                        float gg0 = acc[mf][4 + jf][v]     + bv[2][jf].x;
                        float gg1 = acc[mf][4 + jf][v + 1] + bv[2][jf].y;
                        float go0 = acc[mf][6 + jf][v]     + bv[3][jf].x;
                        float go1 = acc[mf][6 + jf][v + 1] + bv[3][jf].y;
                        int d = bn * 16 + jf * 8 + t4 * 2;
                        size_t gx = (size_t)row * D + d;
                        float2 cc = *(const float2*)&g_c[gx];
                        float c0 = sigm(gf0) * cc.x + sigm(gi0) * ftanh(gg0);
                        float c1 = sigm(gf1) * cc.y + sigm(gi1) * ftanh(gg1);
                        float h0 = sigm(go0) * ftanh(c0);
                        float h1 = sigm(go1) * ftanh(c1);
                        *(float2*)&g_c[gx] = make_float2(c0, c1);
                        *(float2*)&g_h[gx] = make_float2(h0, h1);
                        Ad32[(size_t)bn * PLANEH + (size_t)row * 8 + jf * 4 + t4] = pkhf(h0, h1);
                    }
                }
            }
            // reset accumulators for next tile
            #pragma unroll
            for (int mf = 0; mf < 2; ++mf)
                #pragma unroll
                for (int nf = 0; nf < 8; ++nf)
                    #pragma unroll
                    for (int v = 0; v < 4; ++v) acc[mf][nf][v] = 0.f;
        }
    }
    #undef LOAD_STAGE
}

// ---------------- launch (index 3 = k_gemm it1 for ncu) ----------------
extern "C" void kernel_launch(void* const* d_in, const int* in_sizes, int n_in,
                              void* d_out, int out_size) {
    const float* x    = (const float*)d_in[0];
    const void*  batch=               d_in[1];
    const float* w_ih = (const float*)d_in[2];
    const float* w_hh = (const float*)d_in[3];
    const float* b_ih = (const float*)d_in[4];
    const float* b_hh = (const float*)d_in[5];
    (void)in_sizes; (void)n_in; (void)out_size;

    cudaFuncSetAttribute(k_gemm, cudaFuncAttributeMaxDynamicSharedMemorySize, SMEM_GEMM);

    dim3 gg(8, MG);
    k_prep<<<(GATES * KDIM + 255) / 256, 256>>>(w_ih, w_hh, b_ih, b_hh);  // 0
    k_segstart<<<(NNODES + 255) / 256, 256>>>(batch);                     // 1
    k_attn0<<<(BATCH + WPB - 1) / WPB, WPB * 32>>>(x, b_ih, b_hh);        // 2  (iter 0)
    k_gemm<<<gg, 256, SMEM_GEMM>>>(1);                                    // 3  <- ncu target
    k_attn<<<(BATCH + WPB - 1) / WPB, WPB * 32>>>(x, 0);
    for (int it = 2; it < NITER - 1; ++it) {
        k_gemm<<<gg, 256, SMEM_GEMM>>>(it & 1);
        k_attn<<<(BATCH + WPB - 1) / WPB, WPB * 32>>>(x, (it + 1) & 1);
    }
    k_gemm<<<gg, 256, SMEM_GEMM>>>((NITER - 1) & 1);
    k_attn_last<<<(BATCH + WPB - 1) / WPB, WPB * 32>>>(x, (float*)d_out);
}

// round 17
// speedup vs baseline: 1.0643x; 1.0643x over previous
#include <cuda_runtime.h>
#include <cuda_fp16.h>
#include <cstdint>
#include <cstddef>

#define D        128
#define NNODES   1000000
#define BATCH    100000
#define NITER    6
#define GATES    512
#define KDIM     256

#define BM 256
#define MT 391                         // ceil(100000/256)
#define NT 8
#define ROWPAD 100096                  // 391*256
#define PLANEH ((size_t)ROWPAD * 8)    // u32 per chunk plane (fp16)

// smem: B 64 rows x 528 B = 33792 | A 2 stages x 16 KB = 32768
#define SM_B     0
#define SM_A     33792
#define SMEM_GEMM 66560

// ---------------- device scratch ----------------
// A fp16, CHUNK-MAJOR: [parity][chunk 0..15][row][8 u32 = 16 fp16]
__device__ __align__(16) uint32_t g_Ah[2][16 * PLANEH];   // .bss zero; padding rows stay zero
__device__ float          g_h[BATCH * D];
__device__ float          g_c[BATCH * D];
__device__ __align__(16) __half g_Wh[GATES * KDIM];       // gate-permuted fp16 weights
__device__ float          g_bias[GATES];                   // gate-permuted
__device__ int            g_segstart[BATCH + 1];

// ---------------- helpers ----------------
__device__ __forceinline__ uint32_t pkhf(float a, float b) {
    __half2 h = __floats2half2_rn(a, b);
    return *reinterpret_cast<uint32_t*>(&h);
}
__device__ __forceinline__ float sigm(float v) { return 1.f / (1.f + __expf(-v)); }
__device__ __forceinline__ float ftanh(float v) { return 1.f - 2.f / (__expf(2.f * v) + 1.f); }

__device__ __forceinline__ void mma_fp16(float* d, const uint32_t* a, uint32_t b0, uint32_t b1) {
    asm volatile(
        "mma.sync.aligned.m16n8k16.row.col.f32.f16.f16.f32 "
        "{%0,%1,%2,%3}, {%4,%5,%6,%7}, {%8,%9}, {%0,%1,%2,%3};\n"
        : "+f"(d[0]), "+f"(d[1]), "+f"(d[2]), "+f"(d[3])
        : "r"(a[0]), "r"(a[1]), "r"(a[2]), "r"(a[3]), "r"(b0), "r"(b1));
}
__device__ __forceinline__ void ldsm4(uint32_t& r0, uint32_t& r1, uint32_t& r2, uint32_t& r3,
                                      uint32_t addr) {
    asm volatile("ldmatrix.sync.aligned.m8n8.x4.shared.b16 {%0,%1,%2,%3}, [%4];"
                 : "=r"(r0), "=r"(r1), "=r"(r2), "=r"(r3) : "r"(addr));
}
__device__ __forceinline__ void cpa16s(uint32_t saddr, const void* g) {
    asm volatile("cp.async.cg.shared.global [%0], [%1], 16;\n" :: "r"(saddr), "l"(g));
}
#define CPA_COMMIT asm volatile("cp.async.commit_group;\n" ::: "memory")
#define CPA_WAIT0  asm volatile("cp.async.wait_group 0;\n" ::: "memory")

// ---------------- setup ----------------
__global__ void k_segstart(const void* batch) {
    int n = blockIdx.x * blockDim.x + threadIdx.x;
    if (n >= NNODES) return;
    const int* p32 = (const int*)batch;
    bool is64 = (p32[500001] == 0 && p32[700001] == 0 && p32[900001] == 0);
    int cur, prev;
    if (is64) {
        const long long* p64 = (const long long*)batch;
        cur  = (int)p64[n];
        prev = (n == 0) ? -1 : (int)p64[n - 1];
    } else {
        cur  = p32[n];
        prev = (n == 0) ? -1 : p32[n - 1];
    }
    for (int b = prev + 1; b <= cur; ++b) g_segstart[b] = n;
    if (n == NNODES - 1)
        for (int b = cur + 1; b <= BATCH; ++b) g_segstart[b] = NNODES;
}

// weight prep split in two launches (launch-index alignment for ncu).
// perm: p = bn*64 + gt*16 + j  <->  n = gt*128 + bn*16 + j
__global__ void k_prep_w(const float* __restrict__ w_ih, const float* __restrict__ w_hh) {
    int i = blockIdx.x * blockDim.x + threadIdx.x;
    if (i >= GATES * KDIM) return;
    int p = i / KDIM, k = i % KDIM;
    int bn = p >> 6, rem = p & 63, gt = rem >> 4, j = rem & 15;
    int n = gt * 128 + bn * 16 + j;
    float w = w_ih[n * KDIM + k];
    if (k < D) w += w_hh[n * D + k];
    g_Wh[i] = __float2half_rn(w);
}
__global__ void k_prep_b(const float* __restrict__ b_ih, const float* __restrict__ b_hh) {
    int i = blockIdx.x * blockDim.x + threadIdx.x;
    if (i >= GATES) return;
    int bn = i >> 6, rem = i & 63, gt = rem >> 4, j = rem & 15;
    int n = gt * 128 + bn * 16 + j;
    g_bias[i] = b_ih[n] + b_hh[n];
}

// ---------------- attention core: max-free, 8 nodes / iteration ----------------
// If outp != nullptr (final iteration) write q_star = [h | readout] directly;
// else write the fp16 readout into the A staging planes for the next GEMM.
__device__ __forceinline__ void attn_core(const float* __restrict__ x, int b,
                                          int s0, int s1, int lane,
                                          const float4 hv[4], uint32_t* Ad32,
                                          float* outp) {
    int nsub = lane & 3, q = lane >> 2;
    const float4* x4 = (const float4*)x;
    const float4 z4 = make_float4(0.f, 0.f, 0.f, 0.f);
    float ssum = 0.f;
    float4 acc[4];
    #pragma unroll
    for (int j = 0; j < 4; ++j) acc[j] = z4;

    for (int base = s0; base < s1; base += 8) {
        int na = base + nsub, nb = base + 4 + nsub;
        bool va = na < s1, vb = nb < s1;
        float4 xv[4], yv[4];
        if (va) {
            size_t off = (size_t)na * 32 + q * 4;
            #pragma unroll
            for (int j = 0; j < 4; ++j) xv[j] = x4[off + j];
        } else {
            #pragma unroll
            for (int j = 0; j < 4; ++j) xv[j] = z4;
        }
        if (vb) {
            size_t off = (size_t)nb * 32 + q * 4;
            #pragma unroll
            for (int j = 0; j < 4; ++j) yv[j] = x4[off + j];
        } else {
            #pragma unroll
            for (int j = 0; j < 4; ++j) yv[j] = z4;
        }

        float p1 = 0.f, p2 = 0.f;
        #pragma unroll
        for (int j = 0; j < 4; ++j) {
            p1 += xv[j].x * hv[j].x + xv[j].y * hv[j].y + xv[j].z * hv[j].z + xv[j].w * hv[j].w;
            p2 += yv[j].x * hv[j].x + yv[j].y * hv[j].y + yv[j].z * hv[j].z + yv[j].w * hv[j].w;
        }
        #pragma unroll
        for (int st = 4; st <= 16; st <<= 1) {
            p1 += __shfl_xor_sync(0xffffffffu, p1, st);
            p2 += __shfl_xor_sync(0xffffffffu, p2, st);
        }
        float a1 = va ? __expf(p1 - 20.f) : 0.f;
        float a2 = vb ? __expf(p2 - 20.f) : 0.f;
        ssum += a1 + a2;
        #pragma unroll
        for (int j = 0; j < 4; ++j) {
            acc[j].x += a1 * xv[j].x + a2 * yv[j].x;
            acc[j].y += a1 * xv[j].y + a2 * yv[j].y;
            acc[j].z += a1 * xv[j].z + a2 * yv[j].z;
            acc[j].w += a1 * xv[j].w + a2 * yv[j].w;
        }
    }

    #pragma unroll
    for (int j = 0; j < 4; ++j) {
        #pragma unroll
        for (int st = 1; st < 4; st <<= 1) {
            acc[j].x += __shfl_xor_sync(0xffffffffu, acc[j].x, st);
            acc[j].y += __shfl_xor_sync(0xffffffffu, acc[j].y, st);
            acc[j].z += __shfl_xor_sync(0xffffffffu, acc[j].z, st);
            acc[j].w += __shfl_xor_sync(0xffffffffu, acc[j].w, st);
        }
    }
    ssum += __shfl_xor_sync(0xffffffffu, ssum, 1);
    ssum += __shfl_xor_sync(0xffffffffu, ssum, 2);
    float inv = (ssum > 0.f) ? 1.f / ssum : 0.f;

    if (nsub == 0) {
        if (outp) {
            float4* o4 = (float4*)outp;
            #pragma unroll
            for (int j = 0; j < 4; ++j) o4[(size_t)b * 64 + q * 4 + j] = hv[j];
            #pragma unroll
            for (int j = 0; j < 4; ++j) {
                float4 v2 = acc[j];
                v2.x *= inv; v2.y *= inv; v2.z *= inv; v2.w *= inv;
                o4[(size_t)b * 64 + 32 + q * 4 + j] = v2;
            }
        } else {
            float f[16];
            #pragma unroll
            for (int j = 0; j < 4; ++j) {
                f[j * 4]     = acc[j].x * inv;
                f[j * 4 + 1] = acc[j].y * inv;
                f[j * 4 + 2] = acc[j].z * inv;
                f[j * 4 + 3] = acc[j].w * inv;
            }
            uint32_t hi[8];
            #pragma unroll
            for (int u = 0; u < 8; ++u) hi[u] = pkhf(f[2 * u], f[2 * u + 1]);
            uint4* dst = (uint4*)(Ad32 + (size_t)(8 + q) * PLANEH + (size_t)b * 8);
            dst[0] = make_uint4(hi[0], hi[1], hi[2], hi[3]);
            dst[1] = make_uint4(hi[4], hi[5], hi[6], hi[7]);
        }
    }
}

#define WPB 8
__global__ __launch_bounds__(WPB * 32, 3) void k_attn0(const float* __restrict__ x,
                                                       const float* __restrict__ b_ih,
                                                       const float* __restrict__ b_hh) {
    int warp = threadIdx.x >> 5, lane = threadIdx.x & 31;
    int b = blockIdx.x * WPB + warp;
    if (b >= BATCH) return;
    int nsub = lane & 3, q = lane >> 2;

    float hvf[16], cvf[16];
    #pragma unroll
    for (int t = 0; t < 16; ++t) {
        int d = q * 16 + t;
        float gi = b_ih[d]       + b_hh[d];
        float gg = b_ih[256 + d] + b_hh[256 + d];
        float go = b_ih[384 + d] + b_hh[384 + d];
        float c  = sigm(gi) * ftanh(gg);
        cvf[t] = c;
        hvf[t] = sigm(go) * ftanh(c);
    }
    float4 hv[4];
    #pragma unroll
    for (int j = 0; j < 4; ++j)
        hv[j] = make_float4(hvf[j * 4], hvf[j * 4 + 1], hvf[j * 4 + 2], hvf[j * 4 + 3]);

    uint32_t* Ad32 = g_Ah[1];
    if (nsub == 0) {
        #pragma unroll
        for (int j = 0; j < 4; ++j) {
            ((float4*)g_h)[b * 32 + q * 4 + j] = hv[j];
            ((float4*)g_c)[b * 32 + q * 4 + j] =
                make_float4(cvf[j * 4], cvf[j * 4 + 1], cvf[j * 4 + 2], cvf[j * 4 + 3]);
        }
        uint32_t hi[8];
        #pragma unroll
        for (int u = 0; u < 8; ++u) hi[u] = pkhf(hvf[2 * u], hvf[2 * u + 1]);
        uint4* dst = (uint4*)(Ad32 + (size_t)q * PLANEH + (size_t)b * 8);
        dst[0] = make_uint4(hi[0], hi[1], hi[2], hi[3]);
        dst[1] = make_uint4(hi[4], hi[5], hi[6], hi[7]);
    }

    int s0 = g_segstart[b], s1 = g_segstart[b + 1];
    attn_core(x, b, s0, s1, lane, hv, Ad32, nullptr);
}

__global__ __launch_bounds__(WPB * 32, 3) void k_attn(const float* __restrict__ x, int pn) {
    int warp = threadIdx.x >> 5, lane = threadIdx.x & 31;
    int b = blockIdx.x * WPB + warp;
    if (b >= BATCH) return;
    int q = lane >> 2;
    float4 hv[4];
    #pragma unroll
    for (int j = 0; j < 4; ++j) hv[j] = ((const float4*)g_h)[b * 32 + q * 4 + j];
    int s0 = g_segstart[b], s1 = g_segstart[b + 1];
    attn_core(x, b, s0, s1, lane, hv, g_Ah[pn], nullptr);
}

// final-iteration variant writes q_star straight to d_out
__global__ __launch_bounds__(WPB * 32, 3) void k_attn_last(const float* __restrict__ x,
                                                           float* __restrict__ outp) {
    int warp = threadIdx.x >> 5, lane = threadIdx.x & 31;
    int b = blockIdx.x * WPB + warp;
    if (b >= BATCH) return;
    int q = lane >> 2;
    float4 hv[4];
    #pragma unroll
    for (int j = 0; j < 4; ++j) hv[j] = ((const float4*)g_h)[b * 32 + q * 4 + j];
    int s0 = g_segstart[b], s1 = g_segstart[b + 1];
    attn_core(x, b, s0, s1, lane, hv, nullptr, outp);
}

// ---------------- fused GEMM + LSTM: R11 structure (fp16 1-pass, ldmatrix, 2-stage) ----------------
__global__ __launch_bounds__(256, 2) void k_gemm(int p) {
    extern __shared__ char smem[];
    uint32_t sb = (uint32_t)__cvta_generic_to_shared(smem);
    const uint32_t* Asrc = g_Ah[p];
    uint32_t*       Ad32 = g_Ah[p ^ 1];

    int bn = blockIdx.x, bm = blockIdx.y;
    int tid = threadIdx.x, w = tid >> 5, lane = tid & 31;
    int gi = lane >> 3, lr = lane & 7;
    int g = lane >> 2, t4 = lane & 3;
    int row0 = bm * BM;

    // resident B: 64 rows x 512B, stride 528
    {
        const char* Wb = (const char*)(g_Wh + (size_t)(bn * 64) * KDIM);
        #pragma unroll
        for (int t = 0; t < 8; ++t) {
            int e = t * 256 + tid;
            int r = e >> 5, u = e & 31;
            cpa16s(sb + SM_B + r * 528 + u * 16, Wb + (size_t)r * 512 + u * 16);
        }
    }

    // A cp.async affine bases
    uint32_t pu_cp = (tid & 1) ^ ((tid >> 3) & 1);
    uint32_t dA = sb + SM_A + (tid >> 1) * 32 + pu_cp * 16;
    const char* sA0 = (const char*)(Asrc + (size_t)row0 * 8) + (tid >> 1) * 32 + (tid & 1) * 16;

    #pragma unroll
    for (int t = 0; t < 4; ++t)
        cpa16s(dA + t * 4096, sA0 + (size_t)(t >> 1) * (PLANEH * 4) + (t & 1) * 4096);
    CPA_COMMIT;

    float acc[2][8][4];
    #pragma unroll
    for (int mf = 0; mf < 2; ++mf)
        #pragma unroll
        for (int nf = 0; nf < 8; ++nf)
            #pragma unroll
            for (int v = 0; v < 4; ++v) acc[mf][nf][v] = 0.f;

    // ldmatrix address bases (loop-invariant)
    uint32_t aoff[2];
    #pragma unroll
    for (int mf = 0; mf < 2; ++mf) {
        int rowA = w * 32 + mf * 16 + (gi & 1) * 8 + lr;
        aoff[mf] = rowA * 32 + (((gi >> 1) ^ ((rowA >> 2) & 1)) << 4);
    }
    uint32_t bbase = sb + SM_B + ((gi & 1) * 8 + lr) * 528 + (gi >> 1) * 16;

    #pragma unroll 1
    for (int ph = 0; ph < 8; ++ph) {
        CPA_WAIT0;
        __syncthreads();
        if (ph < 7) {
            uint32_t dA2 = dA + ((ph + 1) & 1) * 16384;
            const char* sAp = sA0 + (size_t)(ph + 1) * 2 * (PLANEH * 4);
            #pragma unroll
            for (int t = 0; t < 4; ++t)
                cpa16s(dA2 + t * 4096, sAp + (size_t)(t >> 1) * (PLANEH * 4) + (t & 1) * 4096);
            CPA_COMMIT;
        }

        uint32_t ab = sb + SM_A + (ph & 1) * 16384;
        #pragma unroll
        for (int c = 0; c < 2; ++c) {
            int kc = ph * 2 + c;
            uint32_t ah[2][4], bb[4][4];
            #pragma unroll
            for (int mf = 0; mf < 2; ++mf)
                ldsm4(ah[mf][0], ah[mf][1], ah[mf][2], ah[mf][3], ab + c * 8192 + aoff[mf]);
            #pragma unroll
            for (int np = 0; np < 4; ++np)
                ldsm4(bb[np][0], bb[np][1], bb[np][2], bb[np][3], bbase + np * 8448 + kc * 32);
            #pragma unroll
            for (int mf = 0; mf < 2; ++mf)
                #pragma unroll
                for (int nf = 0; nf < 8; ++nf) {
                    int np = nf >> 1, od = nf & 1;
                    mma_fp16(acc[mf][nf], ah[mf], bb[np][od], bb[np][od + 2]);
                }
        }
    }

    // ---- register-local LSTM epilogue ----
    float2 bv[4][2];
    #pragma unroll
    for (int gt = 0; gt < 4; ++gt)
        #pragma unroll
        for (int jf = 0; jf < 2; ++jf)
            bv[gt][jf] = *(const float2*)&g_bias[bn * 64 + gt * 16 + jf * 8 + t4 * 2];

    int rbase = row0 + w * 32 + g;
    #pragma unroll
    for (int mf = 0; mf < 2; ++mf) {
        #pragma unroll
        for (int half = 0; half < 2; ++half) {
            int row = rbase + mf * 16 + half * 8;
            if (row >= BATCH) continue;
            #pragma unroll
            for (int jf = 0; jf < 2; ++jf) {
                int v = half * 2;
                float gi0 = acc[mf][jf][v]         + bv[0][jf].x;
                float gi1 = acc[mf][jf][v + 1]     + bv[0][jf].y;
                float gf0 = acc[mf][2 + jf][v]     + bv[1][jf].x;
                float gf1 = acc[mf][2 + jf][v + 1] + bv[1][jf].y;
                float gg0 = acc[mf][4 + jf][v]     + bv[2][jf].x;
                float gg1 = acc[mf][4 + jf][v + 1] + bv[2][jf].y;
                float go0 = acc[mf][6 + jf][v]     + bv[3][jf].x;
                float go1 = acc[mf][6 + jf][v + 1] + bv[3][jf].y;
                int d = bn * 16 + jf * 8 + t4 * 2;
                size_t gx = (size_t)row * D + d;
                float2 cc = *(const float2*)&g_c[gx];
                float c0 = sigm(gf0) * cc.x + sigm(gi0) * ftanh(gg0);
                float c1 = sigm(gf1) * cc.y + sigm(gi1) * ftanh(gg1);
                float h0 = sigm(go0) * ftanh(c0);
                float h1 = sigm(go1) * ftanh(c1);
                *(float2*)&g_c[gx] = make_float2(c0, c1);
                *(float2*)&g_h[gx] = make_float2(h0, h1);
                Ad32[(size_t)bn * PLANEH + (size_t)row * 8 + jf * 4 + t4] = pkhf(h0, h1);
            }
        }
    }
}

// ---------------- launch (index 3 = k_attn0 for ncu: attention profile this round) ----------------
extern "C" void kernel_launch(void* const* d_in, const int* in_sizes, int n_in,
                              void* d_out, int out_size) {
    const float* x    = (const float*)d_in[0];
    const void*  batch=               d_in[1];
    const float* w_ih = (const float*)d_in[2];
    const float* w_hh = (const float*)d_in[3];
    const float* b_ih = (const float*)d_in[4];
    const float* b_hh = (const float*)d_in[5];
    (void)in_sizes; (void)n_in; (void)out_size;

    cudaFuncSetAttribute(k_gemm, cudaFuncAttributeMaxDynamicSharedMemorySize, SMEM_GEMM);

    dim3 gg(NT, MT);   // bn fast-varying: A m-tile shared by concurrent blocks
    k_prep_w<<<(GATES * KDIM + 255) / 256, 256>>>(w_ih, w_hh);            // 0
    k_prep_b<<<(GATES + 255) / 256, 256>>>(b_ih, b_hh);                   // 1
    k_segstart<<<(NNODES + 255) / 256, 256>>>(batch);                     // 2
    k_attn0<<<(BATCH + WPB - 1) / WPB, WPB * 32>>>(x, b_ih, b_hh);        // 3  <- ncu target
    k_gemm<<<gg, 256, SMEM_GEMM>>>(1);
    k_attn<<<(BATCH + WPB - 1) / WPB, WPB * 32>>>(x, 0);
    for (int it = 2; it < NITER - 1; ++it) {
        k_gemm<<<gg, 256, SMEM_GEMM>>>(it & 1);
        k_attn<<<(BATCH + WPB - 1) / WPB, WPB * 32>>>(x, (it + 1) & 1);
    }
    k_gemm<<<gg, 256, SMEM_GEMM>>>((NITER - 1) & 1);
    k_attn_last<<<(BATCH + WPB - 1) / WPB, WPB * 32>>>(x, (float*)d_out);
}